// round 4
// baseline (speedup 1.0000x reference)
#include <cuda_runtime.h>
#include <cstdint>

#define D_ 64
#define B_ 64
#define S_ 1024
#define L_ 512
#define O_ 10

typedef unsigned long long u64;

__device__ float g_vL[B_][D_];
__device__ float g_wR[B_][D_];
__device__ __align__(16) float g_WrT[L_ * D_ * D_ * 2];  // transposed + site-reversed W_right

// ---------- transpose: WrT[u][r][l][i] = W_right[(L-1)-u][l][r][i] ----------
__global__ void transpose_wr_kernel(const float* __restrict__ Wr) {
    int u = blockIdx.x;
    int t = (L_ - 1) - u;
    const float2* src = (const float2*)(Wr) + t * (D_ * D_);
    float2* dst = (float2*)(g_WrT) + u * (D_ * D_);
    __shared__ float2 tile[D_ * (D_ + 1)];
    for (int idx = threadIdx.x; idx < D_ * D_; idx += blockDim.x) {
        int l = idx >> 6, r = idx & 63;
        tile[r * (D_ + 1) + l] = src[idx];
    }
    __syncthreads();
    for (int idx = threadIdx.x; idx < D_ * D_; idx += blockDim.x) {
        int rr = idx >> 6, ll = idx & 63;
        dst[idx] = tile[rr * (D_ + 1) + ll];
    }
}

// ---------- chain kernel ----------
// grid 64: side = bx>>5, pair = bx&31 -> batches (2*pair, 2*pair+1).
// 256 threads: r = tid&63 (output index), q = tid>>6 (l-quarter).
// W streamed via LDG into double-buffered registers (no smem staging).
// u-form: usm[l] = (u0_b0, u1_b0, u0_b1, u1_b1) with u_i = v[l]*x_i.
// Inner loop: packed fma.rn.f32x2 acc += (u0,u1)*(W0,W1); v'[r] = acc.lo+acc.hi.
__global__ void __launch_bounds__(256, 1)
chain_kernel(const float* __restrict__ x, const float* __restrict__ Wl) {
    __shared__ float2 xsh[2][L_];
    __shared__ float4 usm[D_];
    __shared__ float4 part[4][D_];

    int tid = threadIdx.x;
    int r = tid & 63;
    int q = tid >> 6;
    int side = blockIdx.x >> 5;
    int pair = blockIdx.x & 31;
    int b0 = pair * 2;

    const float2* xs0 = (const float2*)x + (size_t)b0 * S_ + side * L_;
    const float2* xs1 = (const float2*)x + (size_t)(b0 + 1) * S_ + side * L_;
    for (int i = tid; i < L_; i += 256) { xsh[0][i] = xs0[i]; xsh[1][i] = xs1[i]; }
    __syncthreads();
    if (tid < 64) {
        float4 z = make_float4(0.f, 0.f, 0.f, 0.f);
        if (tid == 0) {   // v = e0 -> u_i[0] = x_i at the first site
            int i0 = side ? (L_ - 1) : 0;
            float2 a = xsh[0][i0], b = xsh[1][i0];
            z = make_float4(a.x, a.y, b.x, b.y);
        }
        usm[tid] = z;
    }
    __syncthreads();

    const u64* W = side ? (const u64*)g_WrT : (const u64*)Wl;
    const u64* wp = W + (q * 16) * 64 + r;     // element (l, r) as packed (W0,W1)
    u64 wreg[2][16];
    #pragma unroll
    for (int j = 0; j < 16; j++) wreg[0][j] = __ldg(wp + j * 64);
    wp += 4096;

    #pragma unroll 2
    for (int s = 0; s < L_; s++) {
        int pb = s & 1;
        if (s < L_ - 1) {                      // prefetch next site into other buffer
            #pragma unroll
            for (int j = 0; j < 16; j++) wreg[pb ^ 1][j] = __ldg(wp + j * 64);
            wp += 4096;
        }
        u64 acc0 = 0ull, acc1 = 0ull;          // (+0.f, +0.f) bit pattern
        const ulonglong2* ub = (const ulonglong2*)&usm[q * 16];
        #pragma unroll
        for (int j = 0; j < 16; j++) {
            ulonglong2 uu = ub[j];             // .x = batch0 (u0,u1), .y = batch1
            asm("fma.rn.f32x2 %0, %1, %2, %0;" : "+l"(acc0) : "l"(uu.x), "l"(wreg[pb][j]));
            asm("fma.rn.f32x2 %0, %1, %2, %0;" : "+l"(acc1) : "l"(uu.y), "l"(wreg[pb][j]));
        }
        ulonglong2 pv; pv.x = acc0; pv.y = acc1;
        *(ulonglong2*)&part[q][r] = pv;        // STS.128
        __syncthreads();
        if (tid < 128) {                       // reducers: (rr, nb)
            int nb = tid >> 6;
            int rr = tid & 63;
            const char* pb0 = (const char*)part + rr * 16 + nb * 8;
            float2 p0 = *(const float2*)(pb0);
            float2 p1 = *(const float2*)(pb0 + 64 * 16);
            float2 p2 = *(const float2*)(pb0 + 128 * 16);
            float2 p3 = *(const float2*)(pb0 + 192 * 16);
            float v = ((p0.x + p0.y) + (p1.x + p1.y)) +
                      ((p2.x + p2.y) + (p3.x + p3.y));
            if (s < L_ - 1) {
                int xi = side ? (L_ - 2 - s) : (s + 1);
                float2 xn = xsh[nb][xi];
                ((float2*)&usm[rr])[nb] = make_float2(v * xn.x, v * xn.y);
            } else {
                if (side) g_wR[b0 + nb][rr] = v;
                else      g_vL[b0 + nb][rr] = v;
            }
        }
        __syncthreads();
    }
}

// ---------- output: out[b][o] = sum_l vL[l] * sum_r core[o][l][r] * wR[r] ----------
__global__ void __launch_bounds__(640, 1)
output_kernel(const float* __restrict__ core, float* __restrict__ out) {
    int b = blockIdx.x;
    int tid = threadIdx.x;          // 640 = 10 o * 64 l
    int o = tid >> 6, l = tid & 63;
    __shared__ float wsh[D_];
    __shared__ float red[O_][2];
    if (tid < 64) wsh[tid] = g_wR[b][tid];
    __syncthreads();
    const float4* c4 = (const float4*)(core + (o * D_ + l) * D_);
    const float4* w4 = (const float4*)wsh;
    float s = 0.f;
    #pragma unroll
    for (int k = 0; k < 16; k++) {
        float4 cv = c4[k], wv = w4[k];
        s += cv.x * wv.x + cv.y * wv.y + cv.z * wv.z + cv.w * wv.w;
    }
    s *= g_vL[b][l];
    #pragma unroll
    for (int off = 16; off; off >>= 1) s += __shfl_xor_sync(0xFFFFFFFFu, s, off);
    if ((tid & 31) == 0) red[o][(tid >> 5) & 1] = s;
    __syncthreads();
    if (tid < O_) out[b * O_ + tid] = red[tid][0] + red[tid][1];
}

extern "C" void kernel_launch(void* const* d_in, const int* in_sizes, int n_in,
                              void* d_out, int out_size) {
    const float* x    = (const float*)d_in[0];   // [64, 1024, 2]
    const float* Wl   = (const float*)d_in[1];   // [512, 64, 64, 2]
    const float* core = (const float*)d_in[2];   // [10, 64, 64]
    const float* Wr   = (const float*)d_in[3];   // [512, 64, 64, 2]
    float* out = (float*)d_out;                  // [64, 10]

    transpose_wr_kernel<<<L_, 256>>>(Wr);
    chain_kernel<<<64, 256>>>(x, Wl);
    output_kernel<<<B_, 640>>>(core, out);
}

// round 5
// speedup vs baseline: 1.7421x; 1.7421x over previous
#include <cuda_runtime.h>
#include <cuda_fp16.h>
#include <cstdint>

#define D_ 64
#define B_ 64
#define S_ 1024
#define L_ 512
#define O_ 10

#define NST 3
#define SITE_U32 4096                        // fp16 site: 64*64 half2 = 16KB
#define SITE_BYTES 16384
#define SITES_PER_STAGE 4
#define STAGE_BYTES (SITE_BYTES * SITES_PER_STAGE)   // 65536
#define NSTAGES 128
#define CLUSTER 4
#define SLICE_BYTES (STAGE_BYTES / CLUSTER)  // 16384 = one site per rank

#define CONS 256
#define TOT 288

// dynamic smem layout
#define OFF_X   (NST * STAGE_BYTES)          // 196608: float2 xsh[512]
#define OFF_V   (OFF_X + 4096)               // float vsh[64]
#define OFF_U   (OFF_V + 256)                // u64 usm[64] (512B, 16B aligned)
#define OFF_P   (OFF_U + 512)                // float2 part[4][64] (2048)
#define OFF_MB  (OFF_P + 2048)
#define SMEM_TOTAL (OFF_MB + 64)

typedef unsigned long long u64;

__device__ float g_vL[B_][D_];
__device__ float g_wR[B_][D_];
// E in half2: [side][site][row][64]; right side pre-transposed + site-reversed
__device__ __align__(16) uint32_t g_E[2 * L_ * SITE_U32];

// ---------- PTX helpers ----------
__device__ __forceinline__ uint32_t smem_u32(const void* p) {
    uint32_t a;
    asm("{ .reg .u64 t; cvta.to.shared.u64 t, %1; cvt.u32.u64 %0, t; }" : "=r"(a) : "l"(p));
    return a;
}
__device__ __forceinline__ uint32_t ctarank() {
    uint32_t r; asm("mov.u32 %0, %%cluster_ctarank;" : "=r"(r)); return r;
}
__device__ __forceinline__ uint32_t elect_one() {
    uint32_t p;
    asm volatile("{ .reg .pred p; elect.sync _|p, 0xFFFFFFFF; selp.b32 %0, 1, 0, p; }" : "=r"(p));
    return p;
}
#define MBARRIER_INIT(addr, cnt) \
    asm volatile("mbarrier.init.shared.b64 [%0], %1;" :: "r"(addr), "r"((uint32_t)(cnt)) : "memory")
#define MBARRIER_EXPECT_TX(addr, tx) \
    asm volatile("mbarrier.arrive.expect_tx.shared.b64 _, [%0], %1;" :: "r"(addr), "r"((uint32_t)(tx)) : "memory")
#define MBARRIER_ARRIVE_CLUSTER(addr, trank) \
    asm volatile("{ .reg .b32 ra; mapa.shared::cluster.u32 ra, %0, %1; " \
                 "mbarrier.arrive.shared::cluster.b64 _, [ra]; }" \
                 :: "r"((uint32_t)(addr)), "r"((uint32_t)(trank)) : "memory")
#define MBARRIER_WAIT_PARITY(addr, par) do { \
    uint32_t _m = (addr), _p = (par), _d; \
    asm volatile("{ .reg .pred p; mbarrier.try_wait.parity.acquire.cta.shared::cta.b64 p, [%1], %2; " \
                 "selp.b32 %0, 1, 0, p; }" : "=r"(_d) : "r"(_m), "r"(_p) : "memory"); \
    if (!_d) { \
        asm volatile("{ .reg .pred P1; WL_%=: mbarrier.try_wait.parity.acquire.cta.shared::cta.b64 P1, [%0], %1, 0x989680; " \
                     "@P1 bra.uni WD_%=; bra.uni WL_%=; WD_%=: }" :: "r"(_m), "r"(_p) : "memory"); \
    } } while (0)
#define MBARRIER_WAIT_PARITY_RELAXED(addr, par) do { \
    uint32_t _m = (addr), _p = (par), _d; \
    asm volatile("{ .reg .pred p; mbarrier.try_wait.parity.relaxed.cta.shared::cta.b64 p, [%1], %2, 0x989680; " \
                 "selp.b32 %0, 1, 0, p; }" : "=r"(_d) : "r"(_m), "r"(_p) : "memory"); \
    if (!_d) { \
        asm volatile("{ .reg .pred P1; WL_%=: mbarrier.try_wait.parity.relaxed.cta.shared::cta.b64 P1, [%0], %1, 0x989680; " \
                     "@P1 bra.uni WD_%=; bra.uni WL_%=; WD_%=: }" :: "r"(_m), "r"(_p) : "memory"); \
    } } while (0)
#define BULK_MC(dst, src, bytes, mbar, mask) \
    asm volatile("cp.async.bulk.shared::cluster.global.mbarrier::complete_tx::bytes.multicast::cluster " \
                 "[%0], [%1], %2, [%3], %4;" \
                 :: "r"((uint32_t)(dst)), "l"(src), "r"((uint32_t)(bytes)), \
                    "r"((uint32_t)(mbar)), "h"((uint16_t)(mask)) : "memory")
#define NAMED_BAR(id, n) asm volatile("bar.sync %0, %1;" :: "r"(id), "r"(n) : "memory")
#define CLUSTER_SYNC() do { \
    asm volatile("barrier.cluster.arrive.aligned;" ::: "memory"); \
    asm volatile("barrier.cluster.wait.aligned;"   ::: "memory"); } while (0)

// ---------- prep: E = W - I, fp16, right side transposed + reversed ----------
// grid 1024: bx<512 -> left site bx; bx>=512 -> right (reversed) site bx-512.
__global__ void prep_kernel(const float* __restrict__ Wl, const float* __restrict__ Wr) {
    int bx = blockIdx.x;
    int tid = threadIdx.x;
    if (bx < L_) {
        const float2* src = (const float2*)Wl + (size_t)bx * (D_ * D_);
        uint32_t* dst = g_E + (size_t)bx * SITE_U32;
        for (int idx = tid; idx < D_ * D_; idx += 256) {
            int l = idx >> 6, r = idx & 63;
            float d = (l == r) ? 1.0f : 0.0f;
            float2 w = src[idx];
            __half2 h = __floats2half2_rn(w.x - d, w.y - d);
            dst[idx] = *(uint32_t*)&h;
        }
    } else {
        int u = bx - L_;
        const float2* src = (const float2*)Wr + (size_t)(L_ - 1 - u) * (D_ * D_);
        uint32_t* dst = g_E + (size_t)(L_ + u) * SITE_U32;
        __shared__ float2 tile[D_ * (D_ + 1)];
        for (int idx = tid; idx < D_ * D_; idx += 256) {
            int l = idx >> 6, r = idx & 63;
            tile[r * (D_ + 1) + l] = src[idx];
        }
        __syncthreads();
        for (int idx = tid; idx < D_ * D_; idx += 256) {
            int rr = idx >> 6, ll = idx & 63;
            float d = (rr == ll) ? 1.0f : 0.0f;
            float2 w = tile[rr * (D_ + 1) + ll];
            __half2 h = __floats2half2_rn(w.x - d, w.y - d);
            dst[idx] = *(uint32_t*)&h;
        }
    }
}

// ---------- chain kernel ----------
// grid 128, cluster 4 (same side): side = bx>>6, b = bx&63.
// v'[r] = v[r]*(x0+x1) + sum_l [ (v[l]x0)*E0[l,r] + (v[l]x1)*E1[l,r] ]
__global__ void __launch_bounds__(TOT, 1)
chain_kernel(const float* __restrict__ x) {
    extern __shared__ char smem[];
    uint32_t sb = smem_u32(smem);
    int tid = threadIdx.x;
    int bx = blockIdx.x;
    int side = bx >> 6;
    int b = bx & 63;
    uint32_t rank = ctarank();

    uint32_t mb_full  = sb + OFF_MB;
    uint32_t mb_empty = sb + OFF_MB + 24;

    if (tid == 0) {
        #pragma unroll
        for (int i = 0; i < NST; i++) {
            MBARRIER_INIT(mb_full  + 8 * i, 1);
            MBARRIER_INIT(mb_empty + 8 * i, CLUSTER);
        }
    }
    // x staged in scan order (right side reversed here -> kernel is side-uniform)
    float2* xsh = (float2*)(smem + OFF_X);
    const float2* xsrc = (const float2*)x + (size_t)b * S_ + side * L_;
    for (int i = tid; i < L_; i += TOT)
        xsh[i] = xsrc[side ? (L_ - 1 - i) : i];
    float* vsh = (float*)(smem + OFF_V);
    u64*   usm = (u64*)(smem + OFF_U);
    float2* part = (float2*)(smem + OFF_P);
    __syncthreads();
    if (tid < 64) {
        vsh[tid] = (tid == 0) ? 1.0f : 0.0f;
        u64 z = 0ull;
        if (tid == 0) {
            float2 x0 = xsh[0];
            asm("mov.b64 %0, {%1, %2};" : "=l"(z) : "f"(x0.x), "f"(x0.y));
        }
        usm[tid] = z;
    }
    __syncthreads();
    CLUSTER_SYNC();     // all mbarriers visible before any multicast

    if (tid >= CONS) {
        // ---- producer warp ----
        const char* Wb = (const char*)g_E + (size_t)side * L_ * SITE_BYTES;
        int slot = 0, ph = 1;
        for (int st = 0; st < NSTAGES; st++) {
            MBARRIER_WAIT_PARITY_RELAXED(mb_empty + 8 * slot, ph);
            const char* src = Wb + (size_t)st * STAGE_BYTES + rank * SLICE_BYTES;
            uint32_t dst = sb + slot * STAGE_BYTES + rank * SLICE_BYTES;
            if (elect_one()) {
                MBARRIER_EXPECT_TX(mb_full + 8 * slot, STAGE_BYTES);
                BULK_MC(dst, src, SLICE_BYTES, mb_full + 8 * slot, 0xF);
            }
            if (++slot == NST) { slot = 0; ph ^= 1; }
        }
    } else {
        // ---- 256 consumers: r = tid&63, q = l-quarter ----
        int r = tid & 63;
        int q = tid >> 6;
        uint32_t wbuf[2][16];
        int slot = 0, ph = 0, s = 0;
        for (int st = 0; st < NSTAGES; st++) {
            MBARRIER_WAIT_PARITY(mb_full + 8 * slot, ph);
            const uint32_t* Wst = (const uint32_t*)(smem + slot * STAGE_BYTES);
            const uint32_t* wp = Wst + (q * 16) * 64 + r;
            #pragma unroll
            for (int j = 0; j < 16; j++) wbuf[0][j] = wp[j * 64];
            #pragma unroll
            for (int sub = 0; sub < SITES_PER_STAGE; sub++) {
                int pb = sub & 1;
                if (sub < SITES_PER_STAGE - 1) {     // prefetch next site's E
                    const uint32_t* wn = Wst + (sub + 1) * SITE_U32 + (q * 16) * 64 + r;
                    #pragma unroll
                    for (int j = 0; j < 16; j++) wbuf[pb ^ 1][j] = wn[j * 64];
                }
                u64 acc = 0ull;
                const ulonglong2* ub = (const ulonglong2*)(usm + q * 16);
                #pragma unroll
                for (int jj = 0; jj < 8; jj++) {
                    ulonglong2 uu = ub[jj];
                    float2 ea = __half22float2(*(__half2*)&wbuf[pb][2 * jj]);
                    float2 eb = __half22float2(*(__half2*)&wbuf[pb][2 * jj + 1]);
                    u64 pa, pc;
                    asm("mov.b64 %0, {%1, %2};" : "=l"(pa) : "f"(ea.x), "f"(ea.y));
                    asm("mov.b64 %0, {%1, %2};" : "=l"(pc) : "f"(eb.x), "f"(eb.y));
                    asm("fma.rn.f32x2 %0, %1, %2, %0;" : "+l"(acc) : "l"(uu.x), "l"(pa));
                    asm("fma.rn.f32x2 %0, %1, %2, %0;" : "+l"(acc) : "l"(uu.y), "l"(pc));
                }
                part[q * 64 + r] = *(float2*)&acc;
                NAMED_BAR(1, CONS);
                if (tid < 64) {
                    float2 p0 = part[r], p1 = part[64 + r],
                           p2 = part[128 + r], p3 = part[192 + r];
                    float2 xc = xsh[s];
                    float vp = ((p0.x + p0.y) + (p1.x + p1.y)) +
                               ((p2.x + p2.y) + (p3.x + p3.y)) +
                               vsh[r] * (xc.x + xc.y);
                    vsh[r] = vp;
                    if (s < L_ - 1) {
                        float2 xn = xsh[s + 1];
                        u64 up;
                        asm("mov.b64 %0, {%1, %2};" : "=l"(up)
                            : "f"(vp * xn.x), "f"(vp * xn.y));
                        usm[r] = up;
                    }
                }
                NAMED_BAR(1, CONS);
                s++;
            }
            if (tid < CLUSTER)
                MBARRIER_ARRIVE_CLUSTER(mb_empty + 8 * slot, tid);
            if (++slot == NST) { slot = 0; ph ^= 1; }
        }
        if (tid < 64) {
            if (side) g_wR[b][tid] = vsh[tid];
            else      g_vL[b][tid] = vsh[tid];
        }
    }
    CLUSTER_SYNC();
}

// ---------- output: out[b][o] = sum_l vL[l] * sum_r core[o][l][r] * wR[r] ----------
__global__ void __launch_bounds__(640, 1)
output_kernel(const float* __restrict__ core, float* __restrict__ out) {
    int b = blockIdx.x;
    int tid = threadIdx.x;          // 640 = 10 o * 64 l
    int o = tid >> 6, l = tid & 63;
    __shared__ float wsh[D_];
    __shared__ float red[O_][2];
    if (tid < 64) wsh[tid] = g_wR[b][tid];
    __syncthreads();
    const float4* c4 = (const float4*)(core + (o * D_ + l) * D_);
    const float4* w4 = (const float4*)wsh;
    float s = 0.f;
    #pragma unroll
    for (int k = 0; k < 16; k++) {
        float4 cv = c4[k], wv = w4[k];
        s += cv.x * wv.x + cv.y * wv.y + cv.z * wv.z + cv.w * wv.w;
    }
    s *= g_vL[b][l];
    #pragma unroll
    for (int off = 16; off; off >>= 1) s += __shfl_xor_sync(0xFFFFFFFFu, s, off);
    if ((tid & 31) == 0) red[o][(tid >> 5) & 1] = s;
    __syncthreads();
    if (tid < O_) out[b * O_ + tid] = red[tid][0] + red[tid][1];
}

extern "C" void kernel_launch(void* const* d_in, const int* in_sizes, int n_in,
                              void* d_out, int out_size) {
    const float* x    = (const float*)d_in[0];   // [64, 1024, 2]
    const float* Wl   = (const float*)d_in[1];   // [512, 64, 64, 2]
    const float* core = (const float*)d_in[2];   // [10, 64, 64]
    const float* Wr   = (const float*)d_in[3];   // [512, 64, 64, 2]
    float* out = (float*)d_out;                  // [64, 10]

    prep_kernel<<<2 * L_, 256>>>(Wl, Wr);

    cudaFuncSetAttribute(chain_kernel,
                         cudaFuncAttributeMaxDynamicSharedMemorySize, SMEM_TOTAL);
    cudaLaunchConfig_t cfg = {};
    cfg.gridDim = dim3(128, 1, 1);
    cfg.blockDim = dim3(TOT, 1, 1);
    cfg.dynamicSmemBytes = SMEM_TOTAL;
    cfg.stream = 0;
    cudaLaunchAttribute at[1];
    at[0].id = cudaLaunchAttributeClusterDimension;
    at[0].val.clusterDim.x = CLUSTER;
    at[0].val.clusterDim.y = 1;
    at[0].val.clusterDim.z = 1;
    cfg.attrs = at;
    cfg.numAttrs = 1;
    cudaLaunchKernelEx(&cfg, chain_kernel, x);

    output_kernel<<<B_, 640>>>(core, out);
}